// round 17
// baseline (speedup 1.0000x reference)
#include <cuda_runtime.h>
#include <cuda_fp16.h>
#include <mma.h>
#include <cstdint>

using namespace nvcuda;

// GraphConvolution: y = A @ (x @ W^T) + b
//   x: (B=4, N=50000, C=128) f32, adj: (2, E=800000) i32, vals: (E,) f32
//   W: (128,128) f32, b: (128,) f32, out: (B,N,128) f32

#define C_DIM 128
#define B_DIM 4
#define N_ROWS 50000
#define E_MAX  800000

// z stored fp16, node-major: z_h[n][b][c] -> 128 uint2 (512 halfs) per node.
__device__ uint2  g_zh[(size_t)N_ROWS * 128];
__device__ int    g_cnt[N_ROWS];
__device__ int    g_rowptr[N_ROWS + 1];
__device__ int    g_ofs[N_ROWS];
__device__ float2 g_edata[E_MAX];
__device__ int    g_bar;          // grid barrier counter (zeroed each call)

// ===========================================================================
// Persistent GEMM z = x @ W^T (wmma fp16 m16n16k16, fp32 accum).
// Grid = 2 CTAs/SM; each CTA stages W to smem ONCE, then loops over
// 128-row tiles: stage A -> mma -> chunked epilogue (two 64-row halves,
// float scratch reuses the A-tile smem region; Ws persists).
// smem: Ws[128][LDAH] halfs + As[128][LDAH] halfs = 69632 B -> 2 CTAs/SM.
// ===========================================================================
#define LDAH 136
#define LDO  132
#define GEMM_SMEM (2 * 128 * LDAH * (int)sizeof(__half))   // 69632 bytes

__global__ __launch_bounds__(256, 2)
void gemm_persist(const float* __restrict__ x, const float* __restrict__ W,
                  int M, int N, int numTiles) {
    extern __shared__ char smemraw[];
    __half* As = (__half*)smemraw;            // [128][LDAH] (also epilogue scratch)
    __half* Ws = As + 128 * LDAH;             // [128][LDAH] persists across tiles
    float*  Os = (float*)smemraw;             // [64][LDO] epilogue chunk scratch

    const int tid = threadIdx.x;
    const int wid = tid >> 5;
    const int wm = wid & 1;
    const int wn = wid >> 1;

    // Stage W once.
    #pragma unroll
    for (int it = 0; it < 16; it++) {
        int idx = tid + it * 256;
        int row = idx >> 5;
        int kq  = idx & 31;
        float4 v = *(const float4*)(W + row * C_DIM + kq * 4);
        __half2 h0 = __floats2half2_rn(v.x, v.y);
        __half2 h1 = __floats2half2_rn(v.z, v.w);
        uint2 p;
        p.x = *(uint32_t*)&h0;
        p.y = *(uint32_t*)&h1;
        *(uint2*)(Ws + row * LDAH + kq * 4) = p;
    }

    for (int t = blockIdx.x; t < numTiles; t += gridDim.x) {
        const long long m0 = (long long)t * 128;

        __syncthreads();   // previous tile's epilogue reads of As/Os done

        // Stage A tile (gmem -> cvt -> smem, no register buffering).
        #pragma unroll
        for (int it = 0; it < 16; it++) {
            int idx = tid + it * 256;
            int row = idx >> 5;
            int kq  = idx & 31;
            long long gm = m0 + row; if (gm >= M) gm = M - 1;
            float4 v = __ldcs((const float4*)(x + gm * C_DIM + kq * 4));
            __half2 h0 = __floats2half2_rn(v.x, v.y);
            __half2 h1 = __floats2half2_rn(v.z, v.w);
            uint2 p;
            p.x = *(uint32_t*)&h0;
            p.y = *(uint32_t*)&h1;
            *(uint2*)(As + row * LDAH + kq * 4) = p;
        }
        __syncthreads();

        wmma::fragment<wmma::accumulator, 16, 16, 16, float> acc[4][2];
        #pragma unroll
        for (int i = 0; i < 4; i++)
            #pragma unroll
            for (int j = 0; j < 2; j++) wmma::fill_fragment(acc[i][j], 0.0f);

        #pragma unroll
        for (int ks = 0; ks < 8; ks++) {
            const int k = ks * 16;
            wmma::fragment<wmma::matrix_a, 16, 16, 16, __half, wmma::row_major> a[4];
            wmma::fragment<wmma::matrix_b, 16, 16, 16, __half, wmma::col_major> b[2];
            #pragma unroll
            for (int i = 0; i < 4; i++)
                wmma::load_matrix_sync(a[i], As + (wm * 64 + i * 16) * LDAH + k, LDAH);
            #pragma unroll
            for (int j = 0; j < 2; j++)
                wmma::load_matrix_sync(b[j], Ws + (wn * 32 + j * 16) * LDAH + k, LDAH);
            #pragma unroll
            for (int i = 0; i < 4; i++)
                #pragma unroll
                for (int j = 0; j < 2; j++)
                    wmma::mma_sync(acc[i][j], a[i], b[j], acc[i][j]);
        }

        // Chunked epilogue: two 64-row halves through Os (reuses As region).
        #pragma unroll
        for (int c = 0; c < 2; c++) {
            __syncthreads();   // As (mma reads) / previous chunk writes done
            if (wm == c) {
                #pragma unroll
                for (int i = 0; i < 4; i++)
                    #pragma unroll
                    for (int j = 0; j < 2; j++)
                        wmma::store_matrix_sync(
                            Os + (i * 16) * LDO + wn * 32 + j * 16,
                            acc[i][j], LDO, wmma::mem_row_major);
            }
            __syncthreads();
            #pragma unroll
            for (int it = 0; it < 8; it++) {
                int idx = tid + it * 256;
                int row = idx >> 5;          // 0..63
                int q   = idx & 31;
                long long gm = m0 + c * 64 + row;
                if (gm < M) {
                    float4 v = *(const float4*)(Os + row * LDO + q * 4);
                    __half2 h0 = __floats2half2_rn(v.x, v.y);
                    __half2 h1 = __floats2half2_rn(v.z, v.w);
                    int b = (int)(gm / N);
                    int n = (int)(gm % N);
                    uint2 pack;
                    pack.x = *(uint32_t*)&h0;
                    pack.y = *(uint32_t*)&h1;
                    g_zh[(size_t)n * 128 + b * 32 + q] = pack;
                }
            }
        }
    }
}

// ===========================================================================
// CSR build (R16 version): k_zero + persistent k_csr with grid barriers.
// ===========================================================================
#define CSR_CTAS 120
#define CSR_THR  256

__global__ void k_zero(int n) {
    int i = blockIdx.x * blockDim.x + threadIdx.x;
    if (i == 0) g_bar = 0;
    for (; i < n; i += gridDim.x * blockDim.x) g_cnt[i] = 0;
}

__device__ __forceinline__ void grid_bar(int target) {
    __syncthreads();
    if (threadIdx.x == 0) {
        __threadfence();
        atomicAdd(&g_bar, 1);
        while (atomicAdd(&g_bar, 0) < target) __nanosleep(64);
    }
    __syncthreads();
}

__global__ __launch_bounds__(CSR_THR)
void k_csr(const int* __restrict__ rows, const int* __restrict__ cols,
           const float* __restrict__ vals, int E, int n) {
    const int tid  = blockIdx.x * blockDim.x + threadIdx.x;
    const int nthr = gridDim.x * blockDim.x;

    for (int e = tid; e < E; e += nthr)
        atomicAdd(&g_cnt[rows[e]], 1);

    grid_bar(CSR_CTAS);

    if (blockIdx.x == 0) {
        __shared__ int s[CSR_THR];
        const int t = threadIdx.x;
        const int chunk = (n + CSR_THR - 1) / CSR_THR;
        const int base = t * chunk;
        int sum = 0;
        for (int j = 0; j < chunk; j++) {
            int r = base + j;
            if (r < n) sum += g_cnt[r];
        }
        s[t] = sum;
        __syncthreads();
        #pragma unroll
        for (int d = 1; d < CSR_THR; d <<= 1) {
            int v = (t >= d) ? s[t - d] : 0;
            __syncthreads();
            s[t] += v;
            __syncthreads();
        }
        int run = s[t] - sum;
        for (int j = 0; j < chunk; j++) {
            int r = base + j;
            if (r < n) {
                g_rowptr[r] = run;
                g_ofs[r]    = run;
                run += g_cnt[r];
            }
        }
        if (t == 0) g_rowptr[n] = E;
        __threadfence();
    }

    grid_bar(2 * CSR_CTAS);

    for (int e = tid; e < E; e += nthr) {
        int r = rows[e];
        int pos = atomicAdd(&g_ofs[r], 1);
        float2 ed;
        ed.x = __int_as_float(cols[e]);
        ed.y = vals[e];
        g_edata[pos] = ed;
    }
}

// ===========================================================================
// Gather (R9/R13/R16 version — known-good): 2 warps per row, warp covers
// 2 batches, 2-way unrolled, fp32 accumulate, bias fused, streaming stores.
// ===========================================================================
__device__ __forceinline__ void accum_pair(const uint2* __restrict__ src,
                                           int lane, float v,
                                           float4& a0, float4& a1) {
    uint2 p0 = __ldg(src + lane);
    uint2 p1 = __ldg(src + lane + 32);
    float2 fa, fb;
    fa = __half22float2(*(__half2*)&p0.x); fb = __half22float2(*(__half2*)&p0.y);
    a0.x = fmaf(v, fa.x, a0.x); a0.y = fmaf(v, fa.y, a0.y);
    a0.z = fmaf(v, fb.x, a0.z); a0.w = fmaf(v, fb.y, a0.w);
    fa = __half22float2(*(__half2*)&p1.x); fb = __half22float2(*(__half2*)&p1.y);
    a1.x = fmaf(v, fa.x, a1.x); a1.y = fmaf(v, fa.y, a1.y);
    a1.z = fmaf(v, fb.x, a1.z); a1.w = fmaf(v, fb.y, a1.w);
}

__global__ __launch_bounds__(256)
void k_gather(const float* __restrict__ bias, float* __restrict__ out, int N) {
    int gw   = (blockIdx.x * blockDim.x + threadIdx.x) >> 5;
    int lane = threadIdx.x & 31;
    int r    = gw >> 1;
    int half = gw & 1;          // 0: batches {0,1}, 1: batches {2,3}
    if (r >= N) return;
    const int boff = half * 64; // uint2 offset into node block

    float4 acc0 = make_float4(0.f, 0.f, 0.f, 0.f);
    float4 acc1 = acc0, bcc0 = acc0, bcc1 = acc0;

    const int start = g_rowptr[r];
    const int end   = g_rowptr[r + 1];

    int i = start;
    for (; i + 2 <= end; i += 2) {
        float2 e0 = __ldg(&g_edata[i]);
        float2 e1 = __ldg(&g_edata[i + 1]);
        const uint2* s0 = g_zh + (size_t)__float_as_int(e0.x) * 128 + boff;
        const uint2* s1 = g_zh + (size_t)__float_as_int(e1.x) * 128 + boff;
        accum_pair(s0, lane, e0.y, acc0, acc1);
        accum_pair(s1, lane, e1.y, bcc0, bcc1);
    }
    if (i < end) {
        float2 e0 = __ldg(&g_edata[i]);
        const uint2* s0 = g_zh + (size_t)__float_as_int(e0.x) * 128 + boff;
        accum_pair(s0, lane, e0.y, acc0, acc1);
    }

    float4 bv = ((const float4*)bias)[lane];
    acc0.x += bcc0.x + bv.x; acc0.y += bcc0.y + bv.y;
    acc0.z += bcc0.z + bv.z; acc0.w += bcc0.w + bv.w;
    acc1.x += bcc1.x + bv.x; acc1.y += bcc1.y + bv.y;
    acc1.z += bcc1.z + bv.z; acc1.w += bcc1.w + bv.w;

    const size_t NB = (size_t)N * 32;   // float4 units per batch
    float4* dst = (float4*)out + (size_t)(half * 2) * NB + (size_t)r * 32 + lane;
    __stcs(dst,      acc0);
    __stcs(dst + NB, acc1);
}

// ===========================================================================
extern "C" void kernel_launch(void* const* d_in, const int* in_sizes, int n_in,
                              void* d_out, int out_size) {
    const float* x    = (const float*)d_in[0];
    const int*   adj  = (const int*)d_in[1];
    const float* vals = (const float*)d_in[2];
    const float* W    = (const float*)d_in[3];
    const float* bias = (const float*)d_in[4];
    float* out = (float*)d_out;

    const int E = in_sizes[2];
    const int N = in_sizes[0] / (B_DIM * C_DIM);
    const int M = B_DIM * N;

    const int* rows = adj;
    const int* cols = adj + E;

    static cudaStream_t s2 = nullptr;
    static cudaEvent_t evFork, evJoin;
    static int nsm = 0;
    if (!s2) {
        cudaStreamCreateWithFlags(&s2, cudaStreamNonBlocking);
        cudaEventCreateWithFlags(&evFork, cudaEventDisableTiming);
        cudaEventCreateWithFlags(&evJoin, cudaEventDisableTiming);
        cudaDeviceGetAttribute(&nsm, cudaDevAttrMultiProcessorCount, 0);
        cudaFuncSetAttribute(gemm_persist,
                             cudaFuncAttributeMaxDynamicSharedMemorySize, GEMM_SMEM);
    }

    // Fork: CSR build on s2, GEMM on the main stream.
    cudaEventRecord(evFork, 0);
    cudaStreamWaitEvent(s2, evFork, 0);

    k_zero<<<64, 256, 0, s2>>>(N);
    k_csr<<<CSR_CTAS, CSR_THR, 0, s2>>>(rows, cols, vals, E, N);
    cudaEventRecord(evJoin, s2);

    // Persistent fp16 GEMM: W staged once per CTA.
    const int numTiles = (M + 127) / 128;
    int grid = 2 * nsm;
    if (grid > numTiles) grid = numTiles;
    gemm_persist<<<grid, 256, GEMM_SMEM>>>(x, W, M, N, numTiles);

    // Join: gather needs both CSR and z.
    cudaStreamWaitEvent(0, evJoin, 0);
    int blocks = (N * 64 + 255) / 256;
    k_gather<<<blocks, 256>>>(bias, out, N);
}